// round 4
// baseline (speedup 1.0000x reference)
#include <cuda_runtime.h>
#include <cuda_bf16.h>
#include <cstdint>

#define BATCH 16384
#define EMBED 256
#define NS    4096
#define VOCAB 50000

// dynamic smem layout (byte offsets)
// A: 4 K-chunks x [128 rows x 64 bf16] XOR-swizzled = 65536
// B: 3 bufs x [128 rows x 64 bf16] swizzled = 49152
// red: 2 x 128 floats = 1024
#define OFF_A   0
#define OFF_B   65536
#define OFF_RED 114688
#define SMEM_NEED 115712
#define NCH 64   // (NS/2)/128 n-tiles * 4 k-chunks

// ---------------- device scratch ----------------
__device__ __align__(16) __nv_bfloat16 g_Bw[NS * EMBED];
__device__ float g_c[NS];
__device__ float g_ps[2][BATCH];

__device__ __forceinline__ float neg_log_ec(float fid) {
    const float inv_logv = 1.0f / logf((float)VOCAB + 1.0f);
    float p  = (logf(fid + 2.0f) - logf(fid + 1.0f)) * inv_logv;
    float ec = -expm1f((float)NS * log1pf(-p));
    return -logf(ec);
}

__device__ __forceinline__ unsigned su32(const void* p) {
    return (unsigned)__cvta_generic_to_shared(p);
}

// ---------------- prep: gather sampled weight rows -> bf16 ----------------
__global__ void k_prep_B(const int* __restrict__ sids, const float* __restrict__ W) {
    int i = blockIdx.x * 256 + threadIdx.x;
    if (i >= NS * 32) return;
    int s  = i >> 5;
    int d8 = (i & 31) << 3;
    int id = sids[s];
    const float4* src = (const float4*)(W + (size_t)id * EMBED + d8);
    float4 x = src[0], y = src[1];
    __align__(16) __nv_bfloat162 p[4];
    p[0] = __floats2bfloat162_rn(x.x, x.y);
    p[1] = __floats2bfloat162_rn(x.z, x.w);
    p[2] = __floats2bfloat162_rn(y.x, y.y);
    p[3] = __floats2bfloat162_rn(y.z, y.w);
    *(uint4*)(g_Bw + (size_t)s * EMBED + d8) = *(const uint4*)p;
}

__global__ void k_prep_c(const int* __restrict__ sids, const float* __restrict__ bias) {
    int s = blockIdx.x * 256 + threadIdx.x;
    if (s >= NS) return;
    int id = sids[s];
    g_c[s] = bias[id] + neg_log_ec((float)id);
}

// ---------------- fused GEMM + softplus + true-logit ----------------
// grid 256 = 128 M-tiles x 2 N-halves. 256 thr (8 warps: 4M x 2N).
// A resident (swizzled, 4 K-chunks); B 3-stage cp.async; register epilogue.
__global__ __launch_bounds__(256, 2) void k_gemm(
    const float* __restrict__ emb, const int* __restrict__ tgt,
    const float* __restrict__ W, const float* __restrict__ bias) {
    extern __shared__ __align__(16) char smp[];
    const uint32_t base = su32(smp);

    const int tid  = threadIdx.x;
    const int lane = tid & 31;
    const int w    = tid >> 5;
    const int wm   = w & 3;    // M group of 32
    const int wn   = w >> 2;   // N group of 64
    const int mb   = blockIdx.x >> 1;
    const int half = blockIdx.x & 1;
    const int m0   = mb * 128;
    const int nb0  = half * (NS / 2);

    // ---- B chunk loader: ch=(nt,kb) -> buf ch%3, 128x64 bf16 swizzled ----
    auto loadB = [&](int ch) {
        const int nt = ch >> 2, kb = ch & 3, b = ch % 3;
        const __nv_bfloat16* sb = g_Bw + (size_t)(nb0 + nt * 128) * EMBED + kb * 64;
        #pragma unroll
        for (int it = 0; it < 4; it++) {
            int q = tid + it * 256;          // 0..1023 granules of 16B
            int n = q >> 3, g = q & 7;
            uint32_t dst = base + OFF_B + b * 16384 + n * 128 + (((g ^ n) & 7) << 4);
            const void* src = sb + (size_t)n * EMBED + g * 8;
            asm volatile("cp.async.cg.shared.global [%0], [%1], 16;" :: "r"(dst), "l"(src));
        }
        asm volatile("cp.async.commit_group;");
    };

    loadB(0);
    loadB(1);

    // ---- A: load fp32 emb, convert, swizzled store (4 K-chunks) ----
    #pragma unroll 4
    for (int it = 0; it < 16; it++) {
        int idx = tid + it * 256;            // 0..4095 granules
        int r = idx >> 5, G = idx & 31;      // G: 8-col group 0..31
        int c = G >> 3, g = G & 7;
        const float4* s = (const float4*)(emb + (size_t)(m0 + r) * EMBED + G * 8);
        float4 x = s[0], y = s[1];
        __align__(16) __nv_bfloat162 p[4];
        p[0] = __floats2bfloat162_rn(x.x, x.y);
        p[1] = __floats2bfloat162_rn(x.z, x.w);
        p[2] = __floats2bfloat162_rn(y.x, y.y);
        p[3] = __floats2bfloat162_rn(y.z, y.w);
        *(uint4*)(smp + OFF_A + c * 16384 + r * 128 + (((g ^ r) & 7) << 4)) = *(const uint4*)p;
    }

    // ---- fused true-logit (half==0 CTAs only): 2 threads per row ----
    float trueLoss = 0.0f;
    if (half == 0) {
        int r  = tid >> 1;
        int hd = (tid & 1) * 128;
        int id = tgt[m0 + r];
        const float4* e4 = (const float4*)(emb + (size_t)(m0 + r) * EMBED + hd);
        const float4* w4 = (const float4*)(W + (size_t)id * EMBED + hd);
        float s = 0.0f;
        #pragma unroll 8
        for (int i = 0; i < 32; i++) {
            float4 a = e4[i], b = w4[i];
            s += a.x * b.x + a.y * b.y + a.z * b.z + a.w * b.w;
        }
        s += __shfl_xor_sync(0xffffffffu, s, 1);
        if (!(tid & 1)) {
            float tl = s + bias[id] + neg_log_ec((float)id);
            trueLoss = fmaxf(tl, 0.f) - tl + log1pf(expf(-fabsf(tl)));
        }
    }

    float acc[2][8][4];
    #pragma unroll
    for (int mi = 0; mi < 2; mi++)
        #pragma unroll
        for (int ni = 0; ni < 8; ni++)
            #pragma unroll
            for (int q = 0; q < 4; q++) acc[mi][ni][q] = 0.0f;
    float rs[4] = {0.f, 0.f, 0.f, 0.f};

    for (int ch = 0; ch < NCH; ch++) {
        if (ch < NCH - 1) asm volatile("cp.async.wait_group 1;");
        else              asm volatile("cp.async.wait_group 0;");
        __syncthreads();                    // chunk ch visible; buf (ch+2)%3 free
        if (ch + 2 < NCH) loadB(ch + 2);

        const int kb = ch & 3, buf = ch % 3;
        const uint32_t abase = base + OFF_A + kb * 16384;
        const uint32_t bbase = base + OFF_B + buf * 16384;

        #pragma unroll
        for (int kk = 0; kk < 64; kk += 16) {
            unsigned a[2][4];
            #pragma unroll
            for (int mi = 0; mi < 2; mi++) {
                int rr = wm * 32 + mi * 16 + (lane & 15);
                int gp = (kk >> 3) + (lane >> 4);
                unsigned addr = abase + rr * 128 + (((gp ^ rr) & 7) << 4);
                asm volatile("ldmatrix.sync.aligned.m8n8.x4.shared.b16 {%0,%1,%2,%3}, [%4];\n"
                    : "=r"(a[mi][0]), "=r"(a[mi][1]), "=r"(a[mi][2]), "=r"(a[mi][3])
                    : "r"(addr));
            }
            unsigned b[8][2];
            #pragma unroll
            for (int np = 0; np < 4; np++) {
                int nn = wn * 64 + np * 16 + ((lane >> 4) << 3) + (lane & 7);
                int gp = (kk >> 3) + ((lane >> 3) & 1);
                unsigned addr = bbase + nn * 128 + (((gp ^ nn) & 7) << 4);
                asm volatile("ldmatrix.sync.aligned.m8n8.x4.shared.b16 {%0,%1,%2,%3}, [%4];\n"
                    : "=r"(b[np * 2][0]), "=r"(b[np * 2][1]),
                      "=r"(b[np * 2 + 1][0]), "=r"(b[np * 2 + 1][1])
                    : "r"(addr));
            }
            #pragma unroll
            for (int mi = 0; mi < 2; mi++)
                #pragma unroll
                for (int ni = 0; ni < 8; ni++)
                    asm volatile(
                        "mma.sync.aligned.m16n8k16.row.col.f32.bf16.bf16.f32 "
                        "{%0,%1,%2,%3},{%4,%5,%6,%7},{%8,%9},{%0,%1,%2,%3};\n"
                        : "+f"(acc[mi][ni][0]), "+f"(acc[mi][ni][1]),
                          "+f"(acc[mi][ni][2]), "+f"(acc[mi][ni][3])
                        : "r"(a[mi][0]), "r"(a[mi][1]), "r"(a[mi][2]), "r"(a[mi][3]),
                          "r"(b[ni][0]), "r"(b[ni][1]));
        }

        if (kb == 3) {
            // register softplus epilogue for tile nt = ch>>2
            const int nt = ch >> 2;
            const float* cp = g_c + nb0 + nt * 128 + wn * 64 + (lane & 3) * 2;
            #pragma unroll
            for (int mi = 0; mi < 2; mi++) {
                float lin0 = 0.f, lin1 = 0.f, pr0 = 1.f, pr1 = 1.f;
                #pragma unroll
                for (int ni = 0; ni < 8; ni++) {
                    float2 cf = *(const float2*)(cp + ni * 8);
                    float l0 = acc[mi][ni][0] + cf.x;
                    float l1 = acc[mi][ni][1] + cf.y;
                    float l2 = acc[mi][ni][2] + cf.x;
                    float l3 = acc[mi][ni][3] + cf.y;
                    lin0 += fmaxf(l0, 0.f) + fmaxf(l1, 0.f);
                    lin1 += fmaxf(l2, 0.f) + fmaxf(l3, 0.f);
                    pr0 *= (1.f + __expf(-fabsf(l0))) * (1.f + __expf(-fabsf(l1)));
                    pr1 *= (1.f + __expf(-fabsf(l2))) * (1.f + __expf(-fabsf(l3)));
                    acc[mi][ni][0] = 0.f; acc[mi][ni][1] = 0.f;
                    acc[mi][ni][2] = 0.f; acc[mi][ni][3] = 0.f;
                }
                rs[mi * 2 + 0] += lin0 + __logf(pr0);
                rs[mi * 2 + 1] += lin1 + __logf(pr1);
            }
        }
    }

    // ---- reduce row sums (quad lanes share rows, disjoint cols) ----
    float* red = (float*)(smp + OFF_RED);
    #pragma unroll
    for (int s = 0; s < 4; s++) {
        rs[s] += __shfl_xor_sync(0xffffffffu, rs[s], 1);
        rs[s] += __shfl_xor_sync(0xffffffffu, rs[s], 2);
    }
    __syncthreads();   // all warps past last B read (reuse of smem region is done)
    if ((lane & 3) == 0) {
        #pragma unroll
        for (int s = 0; s < 4; s++) {
            int mi = s >> 1, hi = s & 1;
            int row = wm * 32 + mi * 16 + hi * 8 + (lane >> 2);
            red[wn * 128 + row] = rs[s];
        }
    }
    __syncthreads();
    float tmp = 0.0f;
    if (tid < 128) tmp = red[tid] + red[128 + tid];
    __syncthreads();
    if (!(tid & 1)) red[tid >> 1] = trueLoss;   // rows 0..127
    __syncthreads();
    if (tid < 128)
        g_ps[half][m0 + tid] = tmp + (half == 0 ? red[tid] : 0.0f);
}

// ---------------- final mean ----------------
__global__ void k_final(float* __restrict__ out) {
    __shared__ double redd[256];
    double s = 0.0;
    for (int i = threadIdx.x; i < BATCH; i += 256)
        s += (double)g_ps[0][i] + (double)g_ps[1][i];
    redd[threadIdx.x] = s;
    __syncthreads();
    for (int st = 128; st > 0; st >>= 1) {
        if (threadIdx.x < st) redd[threadIdx.x] += redd[threadIdx.x + st];
        __syncthreads();
    }
    if (threadIdx.x == 0) out[0] = (float)(redd[0] / (double)BATCH);
}

// ---------------- launch ----------------
extern "C" void kernel_launch(void* const* d_in, const int* in_sizes, int n_in,
                              void* d_out, int out_size) {
    const float* emb  = (const float*)d_in[0];
    const int*   tgt  = (const int*)d_in[1];
    const int*   sids = (const int*)d_in[2];
    const float* W    = (const float*)d_in[3];
    const float* bias = (const float*)d_in[4];
    float*       out  = (float*)d_out;

    cudaFuncSetAttribute(k_gemm, cudaFuncAttributeMaxDynamicSharedMemorySize, SMEM_NEED);

    k_prep_B<<<(NS * 32) / 256, 256>>>(sids, W);
    k_prep_c<<<NS / 256, 256>>>(sids, bias);
    k_gemm<<<256, 256, SMEM_NEED>>>(emb, tgt, W, bias);
    k_final<<<1, 256>>>(out);
}

// round 5
// speedup vs baseline: 1.2768x; 1.2768x over previous
#include <cuda_runtime.h>
#include <cuda_bf16.h>
#include <cstdint>

#define BATCH 16384
#define EMBED 256
#define NS    4096
#define VOCAB 50000

#define LDA 264   // A_s row stride (elems): 528B, conflict-free ldmatrix
#define LDB 72    // B_s row stride (elems): 144B, conflict-free ldmatrix
#define SMEM_A_BYTES (128 * LDA * 2)        // 67584
#define SMEM_B_BYTES (2 * 128 * LDB * 2)    // 36864 (double buffered)
#define SMEM_RED_BYTES (2 * 128 * 4)        // 1024
#define SMEM_TOTAL (SMEM_A_BYTES + SMEM_B_BYTES + SMEM_RED_BYTES)

// ---------------- device scratch ----------------
__device__ __align__(16) __nv_bfloat16 g_Bw[NS * EMBED]; // gathered sampled weights, bf16
__device__ float g_c[NS];                                // bias[id] - log(expected_count)
__device__ float g_ps[2][BATCH];                         // per-row partials (2 N-halves)
__device__ float g_true[BATCH];                          // per-row true-logit loss

__device__ __forceinline__ float neg_log_ec(float fid) {
    const float inv_logv = 1.0f / logf((float)VOCAB + 1.0f);
    float p  = (logf(fid + 2.0f) - logf(fid + 1.0f)) * inv_logv;
    float ec = -expm1f((float)NS * log1pf(-p));
    return -logf(ec);
}

__device__ __forceinline__ unsigned su32(const void* p) {
    return (unsigned)__cvta_generic_to_shared(p);
}

// ---------------- fused prep (gather B, offsets c, true logits) ----------------
// blocks [0,512): gather+convert sampled weight rows
// blocks [512,528): c offsets
// blocks [528,1040): true logits, 4 rows per warp
__global__ void k_pre(const int* __restrict__ sids, const float* __restrict__ W,
                      const float* __restrict__ bias, const float* __restrict__ emb,
                      const int* __restrict__ tgt) {
    const int b   = blockIdx.x;
    const int tid = threadIdx.x;
    if (b < 512) {
        int i  = b * 256 + tid;
        int s  = i >> 5;
        int d8 = (i & 31) << 3;
        int id = sids[s];
        const float4* src = (const float4*)(W + (size_t)id * EMBED + d8);
        float4 x = src[0], y = src[1];
        __align__(16) __nv_bfloat162 p[4];
        p[0] = __floats2bfloat162_rn(x.x, x.y);
        p[1] = __floats2bfloat162_rn(x.z, x.w);
        p[2] = __floats2bfloat162_rn(y.x, y.y);
        p[3] = __floats2bfloat162_rn(y.z, y.w);
        *(uint4*)(g_Bw + (size_t)s * EMBED + d8) = *(const uint4*)p;
    } else if (b < 528) {
        int s  = (b - 512) * 256 + tid;
        int id = sids[s];
        g_c[s] = bias[id] + neg_log_ec((float)id);
    } else {
        const int tb   = b - 528;
        const int w    = tid >> 5;
        const int lane = tid & 31;
        const int r0   = (tb * 8 + w) * 4;
        int ids[4];
        #pragma unroll
        for (int j = 0; j < 4; j++) ids[j] = tgt[r0 + j];
        float s[4];
        #pragma unroll
        for (int j = 0; j < 4; j++) {
            const float4* e4 = (const float4*)(emb + (size_t)(r0 + j) * EMBED);
            const float4* w4 = (const float4*)(W + (size_t)ids[j] * EMBED);
            float4 a0 = e4[lane], a1 = e4[lane + 32];
            float4 b0 = w4[lane], b1 = w4[lane + 32];
            s[j] = a0.x*b0.x + a0.y*b0.y + a0.z*b0.z + a0.w*b0.w
                 + a1.x*b1.x + a1.y*b1.y + a1.z*b1.z + a1.w*b1.w;
        }
        #pragma unroll
        for (int off = 16; off > 0; off >>= 1)
            #pragma unroll
            for (int j = 0; j < 4; j++)
                s[j] += __shfl_xor_sync(0xffffffffu, s[j], off);
        if (lane == 0) {
            #pragma unroll
            for (int j = 0; j < 4; j++) {
                float tl = s[j] + bias[ids[j]] + neg_log_ec((float)ids[j]);
                g_true[r0 + j] = fmaxf(tl, 0.f) - tl + log1pf(expf(-fabsf(tl)));
            }
        }
    }
}

// ---------------- fused GEMM + softplus row-sum (round-2 proven) ----------------
__global__ __launch_bounds__(256, 2) void k_gemm(const float* __restrict__ emb) {
    extern __shared__ __align__(16) unsigned char sm[];
    __nv_bfloat16* A_s = (__nv_bfloat16*)sm;
    __nv_bfloat16* B_s = (__nv_bfloat16*)(sm + SMEM_A_BYTES);
    float*         red = (float*)(sm + SMEM_A_BYTES + SMEM_B_BYTES);

    const int tid  = threadIdx.x;
    const int lane = tid & 31;
    const int warp = tid >> 5;
    const int wm   = warp & 3;   // M group of 32
    const int wn   = warp >> 2;  // N group of 64
    const int mb   = blockIdx.x >> 1;
    const int half = blockIdx.x & 1;
    const int m0   = mb * 128;
    const int nb0  = half * (NS / 2);

    // ---- load + convert resident A (128 x 256 fp32 -> bf16) ----
    #pragma unroll 4
    for (int i = 0; i < 32; i++) {
        int idx = tid + i * 256;
        int r = idx >> 6;
        int c = (idx & 63) * 4;
        float4 v = *(const float4*)(emb + (size_t)(m0 + r) * EMBED + c);
        __align__(8) __nv_bfloat162 p[2];
        p[0] = __floats2bfloat162_rn(v.x, v.y);
        p[1] = __floats2bfloat162_rn(v.z, v.w);
        *(uint2*)(A_s + r * LDA + c) = *(const uint2*)p;
    }

    auto load_chunk = [&](int buf, int ch) {
        int nt = ch >> 2, kb = ch & 3;
        const __nv_bfloat16* sb = g_Bw + (size_t)(nb0 + nt * 128) * EMBED + kb * 64;
        #pragma unroll
        for (int i = 0; i < 4; i++) {
            int c = tid + i * 256;
            int n = c >> 3, k8 = (c & 7) * 8;
            unsigned dst = su32(B_s + buf * 128 * LDB + n * LDB + k8);
            const void* src = sb + (size_t)n * EMBED + k8;
            asm volatile("cp.async.cg.shared.global [%0], [%1], 16;\n"
                         :: "r"(dst), "l"(src));
        }
    };

    float acc[2][8][4];
    #pragma unroll
    for (int mi = 0; mi < 2; mi++)
        #pragma unroll
        for (int ni = 0; ni < 8; ni++)
            #pragma unroll
            for (int q = 0; q < 4; q++) acc[mi][ni][q] = 0.0f;
    float rs[4] = {0.f, 0.f, 0.f, 0.f};

    load_chunk(0, 0);
    asm volatile("cp.async.commit_group;\n");
    __syncthreads();   // A_s ready for all

    int buf = 0;
    const int NCH = (NS / 2 / 128) * 4;   // 64 chunks
    for (int ch = 0; ch < NCH; ch++) {
        if (ch + 1 < NCH) {
            load_chunk(buf ^ 1, ch + 1);
            asm volatile("cp.async.commit_group;\n");
            asm volatile("cp.async.wait_group 1;\n");
        } else {
            asm volatile("cp.async.wait_group 0;\n");
        }
        __syncthreads();   // chunk ch visible in B_s[buf]

        const int kb = ch & 3;
        #pragma unroll
        for (int kk = 0; kk < 64; kk += 16) {
            const int kg = kb * 64 + kk;
            unsigned a[2][4];
            #pragma unroll
            for (int mi = 0; mi < 2; mi++) {
                unsigned addr = su32(A_s + (wm * 32 + mi * 16 + (lane & 15)) * LDA
                                         + kg + ((lane >> 4) << 3));
                asm volatile("ldmatrix.sync.aligned.m8n8.x4.shared.b16 {%0,%1,%2,%3}, [%4];\n"
                    : "=r"(a[mi][0]), "=r"(a[mi][1]), "=r"(a[mi][2]), "=r"(a[mi][3])
                    : "r"(addr));
            }
            unsigned b[8][2];
            #pragma unroll
            for (int np = 0; np < 4; np++) {
                unsigned addr = su32(B_s + buf * 128 * LDB
                                     + (wn * 64 + np * 16 + ((lane >> 4) << 3) + (lane & 7)) * LDB
                                     + kk + ((lane >> 3) & 1) * 8);
                asm volatile("ldmatrix.sync.aligned.m8n8.x4.shared.b16 {%0,%1,%2,%3}, [%4];\n"
                    : "=r"(b[np * 2][0]), "=r"(b[np * 2][1]),
                      "=r"(b[np * 2 + 1][0]), "=r"(b[np * 2 + 1][1])
                    : "r"(addr));
            }
            #pragma unroll
            for (int mi = 0; mi < 2; mi++)
                #pragma unroll
                for (int ni = 0; ni < 8; ni++)
                    asm volatile(
                        "mma.sync.aligned.m16n8k16.row.col.f32.bf16.bf16.f32 "
                        "{%0,%1,%2,%3},{%4,%5,%6,%7},{%8,%9},{%0,%1,%2,%3};\n"
                        : "+f"(acc[mi][ni][0]), "+f"(acc[mi][ni][1]),
                          "+f"(acc[mi][ni][2]), "+f"(acc[mi][ni][3])
                        : "r"(a[mi][0]), "r"(a[mi][1]), "r"(a[mi][2]), "r"(a[mi][3]),
                          "r"(b[ni][0]), "r"(b[ni][1]));
        }

        if (kb == 3) {
            const int nt = ch >> 2;
            const float* cp = g_c + nb0 + nt * 128 + wn * 64 + (lane & 3) * 2;
            #pragma unroll
            for (int mi = 0; mi < 2; mi++) {
                float lin0 = 0.f, lin1 = 0.f, pr0 = 1.f, pr1 = 1.f;
                #pragma unroll
                for (int ni = 0; ni < 8; ni++) {
                    float2 cf = *(const float2*)(cp + ni * 8);
                    float l0 = acc[mi][ni][0] + cf.x;
                    float l1 = acc[mi][ni][1] + cf.y;
                    float l2 = acc[mi][ni][2] + cf.x;
                    float l3 = acc[mi][ni][3] + cf.y;
                    lin0 += fmaxf(l0, 0.f) + fmaxf(l1, 0.f);
                    lin1 += fmaxf(l2, 0.f) + fmaxf(l3, 0.f);
                    pr0 *= (1.f + __expf(-fabsf(l0))) * (1.f + __expf(-fabsf(l1)));
                    pr1 *= (1.f + __expf(-fabsf(l2))) * (1.f + __expf(-fabsf(l3)));
                    acc[mi][ni][0] = 0.f; acc[mi][ni][1] = 0.f;
                    acc[mi][ni][2] = 0.f; acc[mi][ni][3] = 0.f;
                }
                rs[mi * 2 + 0] += lin0 + __logf(pr0);
                rs[mi * 2 + 1] += lin1 + __logf(pr1);
            }
        }
        __syncthreads();   // all reads of B_s[buf] done before refill
        buf ^= 1;
    }

    #pragma unroll
    for (int s = 0; s < 4; s++) {
        rs[s] += __shfl_xor_sync(0xffffffffu, rs[s], 1);
        rs[s] += __shfl_xor_sync(0xffffffffu, rs[s], 2);
    }
    if ((lane & 3) == 0) {
        #pragma unroll
        for (int s = 0; s < 4; s++) {
            int mi = s >> 1, hi = s & 1;
            int row = wm * 32 + mi * 16 + hi * 8 + (lane >> 2);
            red[wn * 128 + row] = rs[s];
        }
    }
    __syncthreads();
    if (tid < 128)
        g_ps[half][m0 + tid] = red[tid] + red[128 + tid];
}

// ---------------- final mean: 1024 threads, vectorized ----------------
__global__ void k_final(float* __restrict__ out) {
    __shared__ double redd[1024];
    const int tid = threadIdx.x;
    float s = 0.0f;
    const float4* p0 = (const float4*)g_ps[0];
    const float4* p1 = (const float4*)g_ps[1];
    const float4* p2 = (const float4*)g_true;
    #pragma unroll
    for (int i = 0; i < BATCH / 4 / 1024; i++) {
        int idx = tid + i * 1024;
        float4 a = p0[idx], b = p1[idx], c = p2[idx];
        s += a.x + a.y + a.z + a.w + b.x + b.y + b.z + b.w
           + c.x + c.y + c.z + c.w;
    }
    redd[tid] = (double)s;
    __syncthreads();
    for (int st = 512; st > 0; st >>= 1) {
        if (tid < st) redd[tid] += redd[tid + st];
        __syncthreads();
    }
    if (tid == 0) out[0] = (float)(redd[0] / (double)BATCH);
}

// ---------------- launch ----------------
extern "C" void kernel_launch(void* const* d_in, const int* in_sizes, int n_in,
                              void* d_out, int out_size) {
    const float* emb  = (const float*)d_in[0];
    const int*   tgt  = (const int*)d_in[1];
    const int*   sids = (const int*)d_in[2];
    const float* W    = (const float*)d_in[3];
    const float* bias = (const float*)d_in[4];
    float*       out  = (float*)d_out;

    cudaFuncSetAttribute(k_gemm, cudaFuncAttributeMaxDynamicSharedMemorySize, SMEM_TOTAL);

    k_pre<<<1040, 256>>>(sids, W, bias, emb, tgt);
    k_gemm<<<256, 256, SMEM_TOTAL>>>(emb);
    k_final<<<1, 1024>>>(out);
}

// round 6
// speedup vs baseline: 1.2918x; 1.0118x over previous
#include <cuda_runtime.h>
#include <cuda_bf16.h>
#include <cstdint>

#define BATCH 16384
#define EMBED 256
#define NS    4096
#define VOCAB 50000

#define LDA 264                      // A_s row stride (elems), conflict-free ldmatrix
#define LDB 72                       // B_s row stride (elems)
#define BROWS 64                     // B chunk rows (N per tile)
#define BBUF  (BROWS * LDB * 2)      // 9216 B per buffer
#define OFF_A   0
#define OFF_B   (128 * LDA * 2)      // 67584
#define OFF_RED (OFF_B + 4 * BBUF)   // 104448
#define SMEM_TOTAL (OFF_RED + 1024)  // 105472
#define NCH 128                      // (NS/2)/64 tiles * 4 k-chunks

// ---------------- device scratch ----------------
__device__ __align__(16) __nv_bfloat16 g_Bw[NS * EMBED];
__device__ float g_c[NS];
__device__ float g_ps[2][BATCH];
__device__ float g_true[BATCH];

__device__ __forceinline__ float neg_log_ec(float fid) {
    const float inv_logv = 1.0f / logf((float)VOCAB + 1.0f);
    float p  = (logf(fid + 2.0f) - logf(fid + 1.0f)) * inv_logv;
    float ec = -expm1f((float)NS * log1pf(-p));
    return -logf(ec);
}

__device__ __forceinline__ unsigned su32(const void* p) {
    return (unsigned)__cvta_generic_to_shared(p);
}

// ---------------- fused prep (gather B, offsets c, true logits) ----------------
__global__ void k_pre(const int* __restrict__ sids, const float* __restrict__ W,
                      const float* __restrict__ bias, const float* __restrict__ emb,
                      const int* __restrict__ tgt) {
    const int b   = blockIdx.x;
    const int tid = threadIdx.x;
    if (b < 512) {
        int i  = b * 256 + tid;
        int s  = i >> 5;
        int d8 = (i & 31) << 3;
        int id = sids[s];
        const float4* src = (const float4*)(W + (size_t)id * EMBED + d8);
        float4 x = src[0], y = src[1];
        __align__(16) __nv_bfloat162 p[4];
        p[0] = __floats2bfloat162_rn(x.x, x.y);
        p[1] = __floats2bfloat162_rn(x.z, x.w);
        p[2] = __floats2bfloat162_rn(y.x, y.y);
        p[3] = __floats2bfloat162_rn(y.z, y.w);
        *(uint4*)(g_Bw + (size_t)s * EMBED + d8) = *(const uint4*)p;
    } else if (b < 528) {
        int s  = (b - 512) * 256 + tid;
        int id = sids[s];
        g_c[s] = bias[id] + neg_log_ec((float)id);
    } else {
        const int tb   = b - 528;
        const int w    = tid >> 5;
        const int lane = tid & 31;
        const int r0   = (tb * 8 + w) * 4;
        int ids[4];
        #pragma unroll
        for (int j = 0; j < 4; j++) ids[j] = tgt[r0 + j];
        float s[4];
        #pragma unroll
        for (int j = 0; j < 4; j++) {
            const float4* e4 = (const float4*)(emb + (size_t)(r0 + j) * EMBED);
            const float4* w4 = (const float4*)(W + (size_t)ids[j] * EMBED);
            float4 a0 = e4[lane], a1 = e4[lane + 32];
            float4 b0 = w4[lane], b1 = w4[lane + 32];
            s[j] = a0.x*b0.x + a0.y*b0.y + a0.z*b0.z + a0.w*b0.w
                 + a1.x*b1.x + a1.y*b1.y + a1.z*b1.z + a1.w*b1.w;
        }
        #pragma unroll
        for (int off = 16; off > 0; off >>= 1)
            #pragma unroll
            for (int j = 0; j < 4; j++)
                s[j] += __shfl_xor_sync(0xffffffffu, s[j], off);
        if (lane == 0) {
            #pragma unroll
            for (int j = 0; j < 4; j++) {
                float tl = s[j] + bias[ids[j]] + neg_log_ec((float)ids[j]);
                g_true[r0 + j] = fmaxf(tl, 0.f) - tl + log1pf(expf(-fabsf(tl)));
            }
        }
    }
}

// ---------------- fused GEMM + overlapped softplus epilogue ----------------
// grid 256 = 128 M-tiles x 2 N-halves. 8 warps: 4M(32) x 2N(32). N-tile 64.
// Ping-pong accumulators: tile nt MMAs into acc[nt&1] while epilogue of tile
// nt-1 (acc[other]) is spread over the 4 K-chunks, hiding under tensor work.
__global__ __launch_bounds__(256, 2) void k_gemm(const float* __restrict__ emb) {
    extern __shared__ __align__(16) unsigned char sm[];
    __nv_bfloat16* A_s = (__nv_bfloat16*)sm;
    __nv_bfloat16* B_s = (__nv_bfloat16*)(sm + OFF_B);
    float*         red = (float*)(sm + OFF_RED);

    const int tid  = threadIdx.x;
    const int lane = tid & 31;
    const int warp = tid >> 5;
    const int wm   = warp & 3;    // 32-row group
    const int wn   = warp >> 2;   // 32-col group
    const int mb   = blockIdx.x >> 1;
    const int half = blockIdx.x & 1;
    const int m0   = mb * 128;
    const int nb0  = half * (NS / 2);

    // ---- B chunk loader: ch=(nt,kb) -> buf ch&3, 64 rows x 64 K ----
    auto loadB = [&](int ch) {
        const int nt = ch >> 2, kb = ch & 3;
        const __nv_bfloat16* sb = g_Bw + (size_t)(nb0 + nt * BROWS) * EMBED + kb * 64;
        __nv_bfloat16* bd = B_s + (ch & 3) * BROWS * LDB;
        #pragma unroll
        for (int i = 0; i < 2; i++) {
            int q = tid + i * 256;
            int n = q >> 3, k8 = (q & 7) * 8;
            unsigned dst = su32(bd + n * LDB + k8);
            const void* src = sb + (size_t)n * EMBED + k8;
            asm volatile("cp.async.cg.shared.global [%0], [%1], 16;\n"
                         :: "r"(dst), "l"(src));
        }
        asm volatile("cp.async.commit_group;\n");
    };

    loadB(0);
    loadB(1);

    // ---- load + convert resident A (128 x 256 fp32 -> bf16) ----
    #pragma unroll 4
    for (int i = 0; i < 32; i++) {
        int idx = tid + i * 256;
        int r = idx >> 6;
        int c = (idx & 63) * 4;
        float4 v = *(const float4*)(emb + (size_t)(m0 + r) * EMBED + c);
        __align__(8) __nv_bfloat162 p[2];
        p[0] = __floats2bfloat162_rn(v.x, v.y);
        p[1] = __floats2bfloat162_rn(v.z, v.w);
        *(uint2*)(A_s + r * LDA + c) = *(const uint2*)p;
    }

    float accA[2][4][4], accB[2][4][4];
    #pragma unroll
    for (int mi = 0; mi < 2; mi++)
        #pragma unroll
        for (int ni = 0; ni < 4; ni++)
            #pragma unroll
            for (int q = 0; q < 4; q++) { accA[mi][ni][q] = 0.f; accB[mi][ni][q] = 0.f; }
    float rs[4] = {0.f, 0.f, 0.f, 0.f};
    float pr[4] = {1.f, 1.f, 1.f, 1.f};

    // ---- wait for chunk ch, prefetch ch+2 ----
    auto sync_load = [&](int ch) {
        if (ch < NCH - 1) asm volatile("cp.async.wait_group 1;\n");
        else              asm volatile("cp.async.wait_group 0;\n");
        __syncthreads();
        if (ch + 2 < NCH) loadB(ch + 2);
    };

    // ---- MMA one chunk into acc ----
    auto do_mma = [&](float (&acc)[2][4][4], int ch) {
        const int kb = ch & 3;
        __nv_bfloat16* bb = B_s + (ch & 3) * BROWS * LDB;
        #pragma unroll
        for (int kk = 0; kk < 64; kk += 16) {
            const int kg = kb * 64 + kk;
            unsigned a[2][4];
            #pragma unroll
            for (int mi = 0; mi < 2; mi++) {
                unsigned addr = su32(A_s + (wm * 32 + mi * 16 + (lane & 15)) * LDA
                                         + kg + ((lane >> 4) << 3));
                asm volatile("ldmatrix.sync.aligned.m8n8.x4.shared.b16 {%0,%1,%2,%3}, [%4];\n"
                    : "=r"(a[mi][0]), "=r"(a[mi][1]), "=r"(a[mi][2]), "=r"(a[mi][3])
                    : "r"(addr));
            }
            unsigned b[4][2];
            #pragma unroll
            for (int np = 0; np < 2; np++) {
                unsigned addr = su32(bb + (wn * 32 + np * 16 + ((lane >> 4) << 3) + (lane & 7)) * LDB
                                        + kk + ((lane >> 3) & 1) * 8);
                asm volatile("ldmatrix.sync.aligned.m8n8.x4.shared.b16 {%0,%1,%2,%3}, [%4];\n"
                    : "=r"(b[np * 2][0]), "=r"(b[np * 2][1]),
                      "=r"(b[np * 2 + 1][0]), "=r"(b[np * 2 + 1][1])
                    : "r"(addr));
            }
            #pragma unroll
            for (int mi = 0; mi < 2; mi++)
                #pragma unroll
                for (int ni = 0; ni < 4; ni++)
                    asm volatile(
                        "mma.sync.aligned.m16n8k16.row.col.f32.bf16.bf16.f32 "
                        "{%0,%1,%2,%3},{%4,%5,%6,%7},{%8,%9},{%0,%1,%2,%3};\n"
                        : "+f"(acc[mi][ni][0]), "+f"(acc[mi][ni][1]),
                          "+f"(acc[mi][ni][2]), "+f"(acc[mi][ni][3])
                        : "r"(a[mi][0]), "r"(a[mi][1]), "r"(a[mi][2]), "r"(a[mi][3]),
                          "r"(b[ni][0]), "r"(b[ni][1]));
        }
    };

    // ---- one quarter of the softplus epilogue for a finished tile ----
    auto epi = [&](float (&acc)[2][4][4], int part, const float* cb) {
        const int mi = part >> 1, nj = part & 1;
        const int s0 = mi * 2, s1 = s0 + 1;
        #pragma unroll
        for (int nn = 0; nn < 2; nn++) {
            const int ni = nj * 2 + nn;
            float2 cf = *(const float2*)(cb + ni * 8);
            float l0 = acc[mi][ni][0] + cf.x;
            float l1 = acc[mi][ni][1] + cf.y;
            float l2 = acc[mi][ni][2] + cf.x;
            float l3 = acc[mi][ni][3] + cf.y;
            acc[mi][ni][0] = 0.f; acc[mi][ni][1] = 0.f;
            acc[mi][ni][2] = 0.f; acc[mi][ni][3] = 0.f;
            rs[s0] += fmaxf(l0, 0.f) + fmaxf(l1, 0.f);
            rs[s1] += fmaxf(l2, 0.f) + fmaxf(l3, 0.f);
            pr[s0] = fmaf(pr[s0], __expf(-fabsf(l0)), pr[s0]);
            pr[s0] = fmaf(pr[s0], __expf(-fabsf(l1)), pr[s0]);
            pr[s1] = fmaf(pr[s1], __expf(-fabsf(l2)), pr[s1]);
            pr[s1] = fmaf(pr[s1], __expf(-fabsf(l3)), pr[s1]);
        }
        if (part == 3) {
            #pragma unroll
            for (int s = 0; s < 4; s++) { rs[s] += __logf(pr[s]); pr[s] = 1.f; }
        }
    };

    const float* cw = g_c + nb0 + wn * 32 + (lane & 3) * 2;

    for (int t2 = 0; t2 < 16; t2++) {
        const float* cPrev = cw + (2 * t2 - 1) * 64;   // tile 2*t2-1 offsets
        const float* cEven = cw + (2 * t2) * 64;       // tile 2*t2 offsets
        #pragma unroll
        for (int kb = 0; kb < 4; kb++) {               // tile 2*t2 -> accA
            int ch = t2 * 8 + kb;
            sync_load(ch);
            do_mma(accA, ch);
            if (t2 > 0) epi(accB, kb, cPrev);
        }
        #pragma unroll
        for (int kb = 0; kb < 4; kb++) {               // tile 2*t2+1 -> accB
            int ch = t2 * 8 + 4 + kb;
            sync_load(ch);
            do_mma(accB, ch);
            epi(accA, kb, cEven);
        }
    }
    {   // tail: epilogue of the last tile (31, in accB)
        const float* cLast = cw + 31 * 64;
        #pragma unroll
        for (int kb = 0; kb < 4; kb++) epi(accB, kb, cLast);
    }

    // ---- row-sum reduction ----
    #pragma unroll
    for (int s = 0; s < 4; s++) {
        rs[s] += __shfl_xor_sync(0xffffffffu, rs[s], 1);
        rs[s] += __shfl_xor_sync(0xffffffffu, rs[s], 2);
    }
    __syncthreads();
    if ((lane & 3) == 0) {
        #pragma unroll
        for (int s = 0; s < 4; s++) {
            int mi = s >> 1, hi = s & 1;
            int row = wm * 32 + mi * 16 + hi * 8 + (lane >> 2);
            red[wn * 128 + row] = rs[s];
        }
    }
    __syncthreads();
    if (tid < 128)
        g_ps[half][m0 + tid] = red[tid] + red[128 + tid];
}

// ---------------- final mean: 1024 threads, vectorized ----------------
__global__ void k_final(float* __restrict__ out) {
    __shared__ double redd[1024];
    const int tid = threadIdx.x;
    float s = 0.0f;
    const float4* p0 = (const float4*)g_ps[0];
    const float4* p1 = (const float4*)g_ps[1];
    const float4* p2 = (const float4*)g_true;
    #pragma unroll
    for (int i = 0; i < BATCH / 4 / 1024; i++) {
        int idx = tid + i * 1024;
        float4 a = p0[idx], b = p1[idx], c = p2[idx];
        s += a.x + a.y + a.z + a.w + b.x + b.y + b.z + b.w
           + c.x + c.y + c.z + c.w;
    }
    redd[tid] = (double)s;
    __syncthreads();
    for (int st = 512; st > 0; st >>= 1) {
        if (tid < st) redd[tid] += redd[tid + st];
        __syncthreads();
    }
    if (tid == 0) out[0] = (float)(redd[0] / (double)BATCH);
}

// ---------------- launch ----------------
extern "C" void kernel_launch(void* const* d_in, const int* in_sizes, int n_in,
                              void* d_out, int out_size) {
    const float* emb  = (const float*)d_in[0];
    const int*   tgt  = (const int*)d_in[1];
    const int*   sids = (const int*)d_in[2];
    const float* W    = (const float*)d_in[3];
    const float* bias = (const float*)d_in[4];
    float*       out  = (float*)d_out;

    cudaFuncSetAttribute(k_gemm, cudaFuncAttributeMaxDynamicSharedMemorySize, SMEM_TOTAL);

    k_pre<<<1040, 256>>>(sids, W, bias, emb, tgt);
    k_gemm<<<256, 256, SMEM_TOTAL>>>(emb);
    k_final<<<1, 1024>>>(out);
}

// round 7
// speedup vs baseline: 1.3086x; 1.0130x over previous
#include <cuda_runtime.h>
#include <cuda_bf16.h>
#include <cstdint>

#define BATCH 16384
#define EMBED 256
#define NS    4096
#define VOCAB 50000

// smem: A 4 k-chunks x [128r x 64k bf16] XOR-swizzled = 65536
//       B 3 bufs x [128n x 64k bf16] swizzled = 49152
#define OFF_A   0
#define OFF_B   65536
#define OFF_RED 114688
#define SMEM_TOTAL 115712
#define NCH 64     // (NS/2)/128 n-tiles * 4 k-chunks

// ---------------- device scratch ----------------
__device__ __align__(16) __nv_bfloat16 g_Bw[NS * EMBED];
__device__ float g_c[NS];
__device__ float g_ps[2][BATCH];
__device__ float g_true[BATCH];

__device__ __forceinline__ float neg_log_ec(float fid) {
    const float inv_logv = 1.0f / logf((float)VOCAB + 1.0f);
    float p  = (logf(fid + 2.0f) - logf(fid + 1.0f)) * inv_logv;
    float ec = -expm1f((float)NS * log1pf(-p));
    return -logf(ec);
}

__device__ __forceinline__ unsigned su32(const void* p) {
    return (unsigned)__cvta_generic_to_shared(p);
}

// ---------------- fused prep (gather B, offsets c, true logits) ----------------
__global__ void k_pre(const int* __restrict__ sids, const float* __restrict__ W,
                      const float* __restrict__ bias, const float* __restrict__ emb,
                      const int* __restrict__ tgt) {
    const int b   = blockIdx.x;
    const int tid = threadIdx.x;
    if (b < 512) {
        int i  = b * 256 + tid;
        int s  = i >> 5;
        int d8 = (i & 31) << 3;
        int id = sids[s];
        const float4* src = (const float4*)(W + (size_t)id * EMBED + d8);
        float4 x = src[0], y = src[1];
        __align__(16) __nv_bfloat162 p[4];
        p[0] = __floats2bfloat162_rn(x.x, x.y);
        p[1] = __floats2bfloat162_rn(x.z, x.w);
        p[2] = __floats2bfloat162_rn(y.x, y.y);
        p[3] = __floats2bfloat162_rn(y.z, y.w);
        *(uint4*)(g_Bw + (size_t)s * EMBED + d8) = *(const uint4*)p;
    } else if (b < 528) {
        int s  = (b - 512) * 256 + tid;
        int id = sids[s];
        g_c[s] = bias[id] + neg_log_ec((float)id);
    } else {
        const int tb   = b - 528;
        const int w    = tid >> 5;
        const int lane = tid & 31;
        const int r0   = (tb * 8 + w) * 4;
        int ids[4];
        #pragma unroll
        for (int j = 0; j < 4; j++) ids[j] = tgt[r0 + j];
        float s[4];
        #pragma unroll
        for (int j = 0; j < 4; j++) {
            const float4* e4 = (const float4*)(emb + (size_t)(r0 + j) * EMBED);
            const float4* w4 = (const float4*)(W + (size_t)ids[j] * EMBED);
            float4 a0 = e4[lane], a1 = e4[lane + 32];
            float4 b0 = w4[lane], b1 = w4[lane + 32];
            s[j] = a0.x*b0.x + a0.y*b0.y + a0.z*b0.z + a0.w*b0.w
                 + a1.x*b1.x + a1.y*b1.y + a1.z*b1.z + a1.w*b1.w;
        }
        #pragma unroll
        for (int off = 16; off > 0; off >>= 1)
            #pragma unroll
            for (int j = 0; j < 4; j++)
                s[j] += __shfl_xor_sync(0xffffffffu, s[j], off);
        if (lane == 0) {
            #pragma unroll
            for (int j = 0; j < 4; j++) {
                float tl = s[j] + bias[ids[j]] + neg_log_ec((float)ids[j]);
                g_true[r0 + j] = fmaxf(tl, 0.f) - tl + log1pf(expf(-fabsf(tl)));
            }
        }
    }
}

// ---------------- fused GEMM + softplus row-sum ----------------
// grid 256 = 128 M-tiles x 2 N-halves. 8 warps: 4M(32) x 2N(64). BN=128.
// XOR-swizzled smem; 3-stage B ring (1 sync/chunk); A-frag double buffer.
__global__ __launch_bounds__(256, 2) void k_gemm(const float* __restrict__ emb) {
    extern __shared__ __align__(16) char smp[];
    const uint32_t base = su32(smp);
    float* red = (float*)(smp + OFF_RED);

    const int tid  = threadIdx.x;
    const int lane = tid & 31;
    const int warp = tid >> 5;
    const int wm   = warp & 3;   // 32-row group
    const int wn   = warp >> 2;  // 64-col group
    const int mb   = blockIdx.x >> 1;
    const int half = blockIdx.x & 1;
    const int m0   = mb * 128;
    const int nb0  = half * (NS / 2);

    // ---- B chunk loader: ch=(nt,kb) -> buf ch%3, 128n x 64k swizzled ----
    auto loadB = [&](int ch) {
        const int nt = ch >> 2, kb = ch & 3, b = ch % 3;
        const __nv_bfloat16* sb = g_Bw + (size_t)(nb0 + nt * 128) * EMBED + kb * 64;
        #pragma unroll
        for (int it = 0; it < 4; it++) {
            int q = tid + it * 256;           // 1024 granules of 16B
            int n = q >> 3, g = q & 7;
            uint32_t dst = base + OFF_B + b * 16384 + n * 128 + (((g ^ n) & 7) << 4);
            const void* src = sb + (size_t)n * EMBED + g * 8;
            asm volatile("cp.async.cg.shared.global [%0], [%1], 16;" :: "r"(dst), "l"(src));
        }
        asm volatile("cp.async.commit_group;");
    };

    loadB(0);
    loadB(1);

    // ---- A: load fp32 emb, convert, swizzled store into 4 k-chunks ----
    #pragma unroll 4
    for (int it = 0; it < 16; it++) {
        int idx = tid + it * 256;             // 4096 granules
        int r = idx >> 5, G = idx & 31;
        int c = G >> 3, g = G & 7;
        const float4* s = (const float4*)(emb + (size_t)(m0 + r) * EMBED + G * 8);
        float4 x = s[0], y = s[1];
        __align__(16) __nv_bfloat162 p[4];
        p[0] = __floats2bfloat162_rn(x.x, x.y);
        p[1] = __floats2bfloat162_rn(x.z, x.w);
        p[2] = __floats2bfloat162_rn(y.x, y.y);
        p[3] = __floats2bfloat162_rn(y.z, y.w);
        *(uint4*)(smp + OFF_A + c * 16384 + r * 128 + (((g ^ r) & 7) << 4)) = *(const uint4*)p;
    }

    float acc[2][8][4];
    #pragma unroll
    for (int mi = 0; mi < 2; mi++)
        #pragma unroll
        for (int ni = 0; ni < 8; ni++)
            #pragma unroll
            for (int q = 0; q < 4; q++) acc[mi][ni][q] = 0.0f;
    float rs[4] = {0.f, 0.f, 0.f, 0.f};

    // ---- fragment loaders ----
    auto ldA = [&](unsigned (&a)[2][4], uint32_t abase, int kk) {
        #pragma unroll
        for (int mi = 0; mi < 2; mi++) {
            int rr = wm * 32 + mi * 16 + (lane & 15);
            int gp = (kk >> 3) + (lane >> 4);
            unsigned addr = abase + rr * 128 + (((gp ^ rr) & 7) << 4);
            asm volatile("ldmatrix.sync.aligned.m8n8.x4.shared.b16 {%0,%1,%2,%3}, [%4];\n"
                : "=r"(a[mi][0]), "=r"(a[mi][1]), "=r"(a[mi][2]), "=r"(a[mi][3])
                : "r"(addr));
        }
    };
    auto ldBf = [&](unsigned (&b)[8][2], uint32_t bbase, int kk) {
        #pragma unroll
        for (int np = 0; np < 4; np++) {
            int nn = wn * 64 + np * 16 + ((lane >> 4) << 3) + (lane & 7);
            int gp = (kk >> 3) + ((lane >> 3) & 1);
            unsigned addr = bbase + nn * 128 + (((gp ^ nn) & 7) << 4);
            asm volatile("ldmatrix.sync.aligned.m8n8.x4.shared.b16 {%0,%1,%2,%3}, [%4];\n"
                : "=r"(b[np * 2][0]), "=r"(b[np * 2][1]),
                  "=r"(b[np * 2 + 1][0]), "=r"(b[np * 2 + 1][1])
                : "r"(addr));
        }
    };

    for (int ch = 0; ch < NCH; ch++) {
        if (ch < NCH - 1) asm volatile("cp.async.wait_group 1;");
        else              asm volatile("cp.async.wait_group 0;");
        __syncthreads();                       // chunk ch ready; buf (ch+2)%3 free
        if (ch + 2 < NCH) loadB(ch + 2);

        const int kb = ch & 3;
        const uint32_t abase = base + OFF_A + kb * 16384;
        const uint32_t bbase = base + OFF_B + (ch % 3) * 16384;

        unsigned aF[2][2][4];
        unsigned bF[8][2];
        ldA(aF[0], abase, 0);

        #pragma unroll
        for (int ki = 0; ki < 4; ki++) {
            ldBf(bF, bbase, ki * 16);
            if (ki < 3) ldA(aF[(ki + 1) & 1], abase, (ki + 1) * 16);
            unsigned (&a)[2][4] = aF[ki & 1];
            #pragma unroll
            for (int mi = 0; mi < 2; mi++)
                #pragma unroll
                for (int ni = 0; ni < 8; ni++)
                    asm volatile(
                        "mma.sync.aligned.m16n8k16.row.col.f32.bf16.bf16.f32 "
                        "{%0,%1,%2,%3},{%4,%5,%6,%7},{%8,%9},{%0,%1,%2,%3};\n"
                        : "+f"(acc[mi][ni][0]), "+f"(acc[mi][ni][1]),
                          "+f"(acc[mi][ni][2]), "+f"(acc[mi][ni][3])
                        : "r"(a[mi][0]), "r"(a[mi][1]), "r"(a[mi][2]), "r"(a[mi][3]),
                          "r"(bF[ni][0]), "r"(bF[ni][1]));
        }

        if (kb == 3) {
            const int nt = ch >> 2;
            const float* cp = g_c + nb0 + nt * 128 + wn * 64 + (lane & 3) * 2;
            #pragma unroll
            for (int mi = 0; mi < 2; mi++) {
                float lin0 = 0.f, lin1 = 0.f, pr0 = 1.f, pr1 = 1.f;
                #pragma unroll
                for (int ni = 0; ni < 8; ni++) {
                    float2 cf = *(const float2*)(cp + ni * 8);
                    float l0 = acc[mi][ni][0] + cf.x;
                    float l1 = acc[mi][ni][1] + cf.y;
                    float l2 = acc[mi][ni][2] + cf.x;
                    float l3 = acc[mi][ni][3] + cf.y;
                    lin0 += fmaxf(l0, 0.f) + fmaxf(l1, 0.f);
                    lin1 += fmaxf(l2, 0.f) + fmaxf(l3, 0.f);
                    pr0 *= (1.f + __expf(-fabsf(l0))) * (1.f + __expf(-fabsf(l1)));
                    pr1 *= (1.f + __expf(-fabsf(l2))) * (1.f + __expf(-fabsf(l3)));
                    acc[mi][ni][0] = 0.f; acc[mi][ni][1] = 0.f;
                    acc[mi][ni][2] = 0.f; acc[mi][ni][3] = 0.f;
                }
                rs[mi * 2 + 0] += lin0 + __logf(pr0);
                rs[mi * 2 + 1] += lin1 + __logf(pr1);
            }
        }
    }

    // ---- row-sum reduction ----
    #pragma unroll
    for (int s = 0; s < 4; s++) {
        rs[s] += __shfl_xor_sync(0xffffffffu, rs[s], 1);
        rs[s] += __shfl_xor_sync(0xffffffffu, rs[s], 2);
    }
    __syncthreads();
    if ((lane & 3) == 0) {
        #pragma unroll
        for (int s = 0; s < 4; s++) {
            int mi = s >> 1, hi = s & 1;
            int row = wm * 32 + mi * 16 + hi * 8 + (lane >> 2);
            red[wn * 128 + row] = rs[s];
        }
    }
    __syncthreads();
    if (tid < 128)
        g_ps[half][m0 + tid] = red[tid] + red[128 + tid];
}

// ---------------- final mean: 1024 threads, vectorized ----------------
__global__ void k_final(float* __restrict__ out) {
    __shared__ double redd[1024];
    const int tid = threadIdx.x;
    float s = 0.0f;
    const float4* p0 = (const float4*)g_ps[0];
    const float4* p1 = (const float4*)g_ps[1];
    const float4* p2 = (const float4*)g_true;
    #pragma unroll
    for (int i = 0; i < BATCH / 4 / 1024; i++) {
        int idx = tid + i * 1024;
        float4 a = p0[idx], b = p1[idx], c = p2[idx];
        s += a.x + a.y + a.z + a.w + b.x + b.y + b.z + b.w
           + c.x + c.y + c.z + c.w;
    }
    redd[tid] = (double)s;
    __syncthreads();
    for (int st = 512; st > 0; st >>= 1) {
        if (tid < st) redd[tid] += redd[tid + st];
        __syncthreads();
    }
    if (tid == 0) out[0] = (float)(redd[0] / (double)BATCH);
}

// ---------------- launch ----------------
extern "C" void kernel_launch(void* const* d_in, const int* in_sizes, int n_in,
                              void* d_out, int out_size) {
    const float* emb  = (const float*)d_in[0];
    const int*   tgt  = (const int*)d_in[1];
    const int*   sids = (const int*)d_in[2];
    const float* W    = (const float*)d_in[3];
    const float* bias = (const float*)d_in[4];
    float*       out  = (float*)d_out;

    cudaFuncSetAttribute(k_gemm, cudaFuncAttributeMaxDynamicSharedMemorySize, SMEM_TOTAL);

    k_pre<<<1040, 256>>>(sids, W, bias, emb, tgt);
    k_gemm<<<256, 256, SMEM_TOTAL>>>(emb);
    k_final<<<1, 1024>>>(out);
}